// round 10
// baseline (speedup 1.0000x reference)
#include <cuda_runtime.h>
#include <math.h>

// Problem shapes (fixed by the dataset)
#define N_SRC 8
#define B 4
#define T 2048
#define H 2048
#define THREADS 256          // each thread owns 8 consecutive floats (2 float4)
#define NROWS (B * T)        // 8192 (b,t) rows total
#define EPS 1e-6f
#define PITCH 16
#define CTAS_PER_SM 4        // 4 independent barrier domains per SM

__device__ __forceinline__ void prefetch_l2(const void* p) {
    asm volatile("prefetch.global.L2 [%0];" :: "l"(p));
}

// ---------------------------------------------------------------------------
// Persistent-CTA router, 4 CTAs/SM. Each CTA walks a contiguous strip of
// ~14 (b,t) rows. Two-pass per row:
//   phase 1: read row (__ldg, stays in L1/L2), accumulate {sum v^2, q.v} per n
//   fold-reduce (16 SHFL) + 1 barrier + redundant column-sum + softmax
//   phase 2: re-read row (__ldcs, L1/L2 hit), accumulate routed = sum alpha_n v_n
// Register footprint stays <=64 at 256 threads -> 4 CTAs/SM; the 4 independent
// barrier domains keep the LSU fed through each CTA's reduce tail.
// ---------------------------------------------------------------------------
__global__ __launch_bounds__(THREADS, CTAS_PER_SM)
void router_kernel(const float* __restrict__ values,
                   const float* __restrict__ wq,
                   const float* __restrict__ bias,
                   const int* __restrict__ pos_ptr,
                   float* __restrict__ out_routed,   // [B][T][H]
                   float* __restrict__ out_alpha,    // [B][T][N_SRC]
                   int n_cta) {
    const int tid  = threadIdx.x;
    const int warp = tid >> 5, lane = tid & 31;
    const int pos  = pos_ptr ? *pos_ptr : N_SRC;
    const int j    = tid << 3;                      // 8 floats per thread

    // contiguous strip assignment: first `rem` CTAs get qn+1 rows
    const int qn  = NROWS / n_cta;
    const int rem = NROWS - qn * n_cta;
    const int cta = blockIdx.x;
    const int r0  = cta * qn + min(cta, rem);
    const int r1  = r0 + qn + (cta < rem ? 1 : 0);

    __shared__ float red[2][8 * PITCH];             // double-buffered per-warp totals
    __shared__ float cbred[8][N_SRC + 1];
    __shared__ float cb_s[N_SRC];

    const float4 q0 = *(const float4*)(wq + (size_t)pos * H + j);
    const float4 q1 = *(const float4*)(wq + (size_t)pos * H + j + 4);
    const size_t nstr = (size_t)B * T * H;          // n stride in values

    // prefetch mapping: thread covers 2 x 128B lines of the target row
    const int pf_n   = tid >> 5;                    // n = 0..7
    const int pf_off = (tid & 31) << 6;             // *64 floats = 256B
    const float* pfb = values + (size_t)pf_n * nstr + pf_off;

    const float inv_sqrt_h = rsqrtf((float)H);
    const float inv_h = 1.0f / (float)H;

    // ---- prologue: prefetch first rows + per-CTA cbias ----
    if (r0 + 1 < r1) {
        prefetch_l2(pfb + (size_t)(r0 + 1) * H);
        prefetch_l2(pfb + (size_t)(r0 + 1) * H + 32);
    }
    if (r0 + 2 < r1) {
        prefetch_l2(pfb + (size_t)(r0 + 2) * H);
        prefetch_l2(pfb + (size_t)(r0 + 2) * H + 32);
    }

    {
        float cb[N_SRC];
        #pragma unroll
        for (int n = 0; n < N_SRC; n++) {
            const float4 b0 = __ldg((const float4*)(bias + (size_t)n * H + j));
            const float4 b1 = __ldg((const float4*)(bias + (size_t)n * H + j + 4));
            cb[n] = q0.x*b0.x + q0.y*b0.y + q0.z*b0.z + q0.w*b0.w
                  + q1.x*b1.x + q1.y*b1.y + q1.z*b1.z + q1.w*b1.w;
        }
        #pragma unroll
        for (int n = 0; n < N_SRC; n++) {
            #pragma unroll
            for (int o = 16; o; o >>= 1)
                cb[n] += __shfl_xor_sync(0xffffffffu, cb[n], o);
        }
        if (lane == 0) {
            #pragma unroll
            for (int n = 0; n < N_SRC; n++)
                cbred[warp][n] = cb[n];
        }
        __syncthreads();
        if (warp == 0 && lane < N_SRC) {
            float s = 0.f;
            #pragma unroll
            for (int w = 0; w < 8; w++) s += cbred[w][lane];
            cb_s[lane] = s * inv_sqrt_h;
        }
        __syncthreads();
    }

    // ---- main loop over this CTA's strip ----
    for (int r = r0; r < r1; r++) {
        const size_t rbase = (size_t)r * H;

        // phase 1: read row, accumulate partials (groups of 4 n's, 8 LDG.128)
        float val[16];
        #pragma unroll
        for (int g = 0; g < 2; g++) {
            float4 a[4], bv[4];
            #pragma unroll
            for (int k = 0; k < 4; k++) {
                const float* p = values + rbase + (size_t)(4*g + k) * nstr + j;
                a[k]  = __ldg((const float4*)p);
                bv[k] = __ldg((const float4*)(p + 4));
            }
            #pragma unroll
            for (int k = 0; k < 4; k++) {
                const int n = 4*g + k;
                val[n]     = a[k].x*a[k].x + a[k].y*a[k].y + a[k].z*a[k].z + a[k].w*a[k].w
                           + bv[k].x*bv[k].x + bv[k].y*bv[k].y + bv[k].z*bv[k].z + bv[k].w*bv[k].w;
                val[8 + n] = q0.x*a[k].x + q0.y*a[k].y + q0.z*a[k].z + q0.w*a[k].w
                           + q1.x*bv[k].x + q1.y*bv[k].y + q1.z*bv[k].z + q1.w*bv[k].w;
            }
        }

        // prefetch row r+2 into L2 (in flight through the reduce tail)
        if (r + 2 < r1) {
            prefetch_l2(pfb + (size_t)(r + 2) * H);
            prefetch_l2(pfb + (size_t)(r + 2) * H + 32);
        }

        // fold-reduce: halve value count each level (16 SHFL total)
        {   // o=16: keep 8
            const bool bit = (lane & 16) != 0;
            #pragma unroll
            for (int k = 0; k < 8; k++) {
                const float send = bit ? val[k] : val[8 + k];
                const float recv = __shfl_xor_sync(0xffffffffu, send, 16);
                val[k] = (bit ? val[8 + k] : val[k]) + recv;
            }
        }
        {   // o=8: keep 4
            const bool bit = (lane & 8) != 0;
            #pragma unroll
            for (int k = 0; k < 4; k++) {
                const float send = bit ? val[k] : val[4 + k];
                const float recv = __shfl_xor_sync(0xffffffffu, send, 8);
                val[k] = (bit ? val[4 + k] : val[k]) + recv;
            }
        }
        {   // o=4: keep 2
            const bool bit = (lane & 4) != 0;
            #pragma unroll
            for (int k = 0; k < 2; k++) {
                const float send = bit ? val[k] : val[2 + k];
                const float recv = __shfl_xor_sync(0xffffffffu, send, 4);
                val[k] = (bit ? val[2 + k] : val[k]) + recv;
            }
        }
        float t;
        {   // o=2: keep 1
            const bool bit = (lane & 2) != 0;
            const float send = bit ? val[0] : val[1];
            const float recv = __shfl_xor_sync(0xffffffffu, send, 2);
            t = (bit ? val[1] : val[0]) + recv;
        }
        t += __shfl_xor_sync(0xffffffffu, t, 1);
        // lane L now holds warp total of value index (L>>1)

        float* rb = red[r & 1];
        if ((lane & 1) == 0)
            rb[warp * PITCH + (lane >> 1)] = t;
        __syncthreads();                            // the only barrier per row

        // every warp redundantly sums the 8 warp-partials per column
        float tk = 0.f;
        if (lane < 16) {
            #pragma unroll
            for (int w = 0; w < 8; w++)
                tk += rb[w * PITCH + lane];
        }

        // per-thread softmax over 8 scalars (gather via shuffle; no max-sub)
        float alpha[N_SRC];
        {
            float sum = 0.f;
            #pragma unroll
            for (int n = 0; n < N_SRC; n++) {
                const float sumsq = __shfl_sync(0xffffffffu, tk, n);
                const float dotq  = __shfl_sync(0xffffffffu, tk, 8 + n);
                const float inv   = rsqrtf(sumsq * inv_h + EPS);
                alpha[n] = __expf(dotq * inv * inv_sqrt_h + cb_s[n]);
                sum += alpha[n];
            }
            const float rr = 1.0f / sum;
            #pragma unroll
            for (int n = 0; n < N_SRC; n++) alpha[n] *= rr;
        }

        // phase 2: re-read row (L1/L2 hit), accumulate routed
        float4 o0 = make_float4(0.f, 0.f, 0.f, 0.f);
        float4 o1 = make_float4(0.f, 0.f, 0.f, 0.f);
        #pragma unroll
        for (int g = 0; g < 2; g++) {
            float4 a[4], bv[4];
            #pragma unroll
            for (int k = 0; k < 4; k++) {
                const float* p = values + rbase + (size_t)(4*g + k) * nstr + j;
                a[k]  = __ldcs((const float4*)p);
                bv[k] = __ldcs((const float4*)(p + 4));
            }
            #pragma unroll
            for (int k = 0; k < 4; k++) {
                const float an = alpha[4*g + k];
                o0.x += an * a[k].x;  o0.y += an * a[k].y;
                o0.z += an * a[k].z;  o0.w += an * a[k].w;
                o1.x += an * bv[k].x; o1.y += an * bv[k].y;
                o1.z += an * bv[k].z; o1.w += an * bv[k].w;
            }
        }
        __stcs((float4*)(out_routed + rbase + j), o0);
        __stcs((float4*)(out_routed + rbase + j + 4), o1);

        if (tid < N_SRC)
            out_alpha[(size_t)r * N_SRC + tid] = alpha[tid];
    }
}

// ---------------------------------------------------------------------------
// kernel_launch
// inputs: [0] values f32 [8,4,2048,2048], [1] w_query f32 [12,2048],
//         [2] key_pos_bias f32 [12,2048], [3] position i32 scalar
// output: routed f32 [4,2048,2048] followed by alpha f32 [4,2048,8]
// ---------------------------------------------------------------------------
extern "C" void kernel_launch(void* const* d_in, const int* in_sizes, int n_in,
                              void* d_out, int out_size) {
    const float* values = (const float*)d_in[0];
    const float* wq     = (const float*)d_in[1];
    const float* bias   = (const float*)d_in[2];
    const int*   pos    = (n_in > 3) ? (const int*)d_in[3] : nullptr;

    float* out_routed = (float*)d_out;
    float* out_alpha  = (float*)d_out + (size_t)B * T * H;

    static int n_cta = 0;
    if (n_cta == 0) {
        int dev = 0, nsm = 148;
        cudaGetDevice(&dev);
        cudaDeviceGetAttribute(&nsm, cudaDevAttrMultiProcessorCount, dev);
        n_cta = nsm * CTAS_PER_SM;
    }

    router_kernel<<<n_cta, THREADS>>>(values, wq, bias, pos,
                                      out_routed, out_alpha, n_cta);
}

// round 11
// speedup vs baseline: 1.6054x; 1.6054x over previous
#include <cuda_runtime.h>
#include <math.h>

// Problem shapes (fixed by the dataset)
#define N_SRC 8
#define B 4
#define T 2048
#define H 2048
#define THREADS 512          // H/4 floats per thread
#define NROWS (B * T)        // 8192 (b,t) rows total
#define EPS 1e-6f
#define PITCH 16
#define CTAS_PER_SM 2

__device__ __forceinline__ void prefetch_l2(const void* p) {
    asm volatile("prefetch.global.L2 [%0];" :: "l"(p));
}

// ---------------------------------------------------------------------------
// Persistent-CTA router (R9 skeleton): grid = 2*numSMs, contiguous strips.
// Per row:
//  - loads at loop TOP (8 x LDG.128, front-batched)
//  - L2 prefetch 2 rows ahead
//  - fold-reduce (16 SHFL/thread) + 1 barrier/row (double-buffered red[])
//  - LANE-SPECIALIZED softmax: lane n computes rsqrt/exp for source n only
//    (3 MUFU warp-insts instead of 16), alphas gathered via SHFL.
// ---------------------------------------------------------------------------
__global__ __launch_bounds__(THREADS, CTAS_PER_SM)
void router_kernel(const float* __restrict__ values,
                   const float* __restrict__ wq,
                   const float* __restrict__ bias,
                   const int* __restrict__ pos_ptr,
                   float* __restrict__ out_routed,   // [B][T][H]
                   float* __restrict__ out_alpha,    // [B][T][N_SRC]
                   int n_cta) {
    const int tid  = threadIdx.x;
    const int warp = tid >> 5, lane = tid & 31;
    const int pos  = pos_ptr ? *pos_ptr : N_SRC;
    const int j    = tid << 2;                      // float index within row

    // contiguous strip assignment: first `rem` CTAs get qn+1 rows
    const int qn  = NROWS / n_cta;
    const int rem = NROWS - qn * n_cta;
    const int cta = blockIdx.x;
    const int r0  = cta * qn + min(cta, rem);
    const int r1  = r0 + qn + (cta < rem ? 1 : 0);

    __shared__ float red[2][16 * PITCH];            // double-buffered per-warp totals
    __shared__ float cbred[16][N_SRC + 1];
    __shared__ float cb_s[N_SRC];

    const float4 q = *(const float4*)(wq + (size_t)pos * H + j);
    const size_t nstr = (size_t)B * T * H;          // n stride in values

    // prefetch mapping: thread tid covers one 128B line of the target row
    const int pf_n   = tid >> 6;
    const int pf_off = (tid & 63) << 5;             // *32 floats = 128B line
    const float* pfb = values + (size_t)pf_n * nstr + pf_off;

    const float inv_sqrt_h = rsqrtf((float)H);
    const float inv_h = 1.0f / (float)H;

    // ---- prologue: prefetch first rows + per-CTA cbias ----
    if (r0 + 1 < r1) prefetch_l2(pfb + (size_t)(r0 + 1) * H);
    if (r0 + 2 < r1) prefetch_l2(pfb + (size_t)(r0 + 2) * H);

    {
        float cb[N_SRC];
        #pragma unroll
        for (int n = 0; n < N_SRC; n++) {
            const float4 bv = __ldg((const float4*)(bias + (size_t)n * H + j));
            cb[n] = q.x*bv.x + q.y*bv.y + q.z*bv.z + q.w*bv.w;
        }
        #pragma unroll
        for (int n = 0; n < N_SRC; n++) {
            #pragma unroll
            for (int o = 16; o; o >>= 1)
                cb[n] += __shfl_xor_sync(0xffffffffu, cb[n], o);
        }
        if (lane == 0) {
            #pragma unroll
            for (int n = 0; n < N_SRC; n++)
                cbred[warp][n] = cb[n];
        }
        __syncthreads();
        if (warp == 0 && lane < N_SRC) {
            float s = 0.f;
            #pragma unroll
            for (int w = 0; w < 16; w++) s += cbred[w][lane];
            cb_s[lane] = s * inv_sqrt_h;
        }
        __syncthreads();
    }

    // ---- main loop over this CTA's strip ----
    for (int r = r0; r < r1; r++) {
        const size_t rbase = (size_t)r * H;

        // front-batched loads of this row (8 x LDG.128)
        float4 v[N_SRC];
        #pragma unroll
        for (int n = 0; n < N_SRC; n++)
            v[n] = __ldcs((const float4*)(values + rbase + (size_t)n * nstr + j));

        // prefetch row r+2 into L2 (in flight through the reduce tail)
        if (r + 2 < r1)
            prefetch_l2(pfb + (size_t)(r + 2) * H);

        // per-thread partials: val[0..7] = sum(v^2), val[8..15] = q.v
        float val[16];
        #pragma unroll
        for (int n = 0; n < N_SRC; n++) {
            const float4 x = v[n];
            val[n]     = x.x*x.x + x.y*x.y + x.z*x.z + x.w*x.w;
            val[8 + n] = q.x*x.x + q.y*x.y + q.z*x.z + q.w*x.w;
        }

        // fold-reduce: halve value count each level (16 SHFL total)
        {   // o=16: keep 8
            const bool bit = (lane & 16) != 0;
            #pragma unroll
            for (int k = 0; k < 8; k++) {
                const float send = bit ? val[k] : val[8 + k];
                const float recv = __shfl_xor_sync(0xffffffffu, send, 16);
                val[k] = (bit ? val[8 + k] : val[k]) + recv;
            }
        }
        {   // o=8: keep 4
            const bool bit = (lane & 8) != 0;
            #pragma unroll
            for (int k = 0; k < 4; k++) {
                const float send = bit ? val[k] : val[4 + k];
                const float recv = __shfl_xor_sync(0xffffffffu, send, 8);
                val[k] = (bit ? val[4 + k] : val[k]) + recv;
            }
        }
        {   // o=4: keep 2
            const bool bit = (lane & 4) != 0;
            #pragma unroll
            for (int k = 0; k < 2; k++) {
                const float send = bit ? val[k] : val[2 + k];
                const float recv = __shfl_xor_sync(0xffffffffu, send, 4);
                val[k] = (bit ? val[2 + k] : val[k]) + recv;
            }
        }
        float t;
        {   // o=2: keep 1
            const bool bit = (lane & 2) != 0;
            const float send = bit ? val[0] : val[1];
            const float recv = __shfl_xor_sync(0xffffffffu, send, 2);
            t = (bit ? val[1] : val[0]) + recv;
        }
        t += __shfl_xor_sync(0xffffffffu, t, 1);
        // lane L now holds warp total of value index (L>>1)

        float* rb = red[r & 1];
        if ((lane & 1) == 0)
            rb[warp * PITCH + (lane >> 1)] = t;
        __syncthreads();                            // the only barrier per row

        // every warp redundantly sums the 16 columns
        float tk = 0.f;
        if (lane < 16) {
            #pragma unroll
            for (int w = 0; w < 16; w++)
                tk += rb[w * PITCH + lane];
        }

        // lane-specialized softmax: lane n (n<8) computes exp for source n only
        // (garbage in lanes >=8 is never read)
        float e;
        {
            const float dotq = __shfl_sync(0xffffffffu, tk, 8 + (lane & 7));
            const float inv  = rsqrtf(tk * inv_h + EPS);          // 1 MUFU/warp
            e = __expf(dotq * inv * inv_sqrt_h + cb_s[lane & 7]); // 1 MUFU/warp
        }
        // sum over lanes 0..7 (butterfly within the 8-lane group)
        float s = e;
        s += __shfl_xor_sync(0xffffffffu, s, 4);
        s += __shfl_xor_sync(0xffffffffu, s, 2);
        s += __shfl_xor_sync(0xffffffffu, s, 1);
        const float rr = 1.0f / __shfl_sync(0xffffffffu, s, 0);   // 1 MUFU/warp

        // gather alphas (valid lanes 0..7 of e)
        float alpha[N_SRC];
        #pragma unroll
        for (int n = 0; n < N_SRC; n++)
            alpha[n] = __shfl_sync(0xffffffffu, e, n) * rr;

        // routed = sum_n alpha_n * v_n  (register-resident), streaming store
        float4 o;
        o.x = alpha[0]*v[0].x; o.y = alpha[0]*v[0].y;
        o.z = alpha[0]*v[0].z; o.w = alpha[0]*v[0].w;
        #pragma unroll
        for (int n = 1; n < N_SRC; n++) {
            o.x += alpha[n]*v[n].x;
            o.y += alpha[n]*v[n].y;
            o.z += alpha[n]*v[n].z;
            o.w += alpha[n]*v[n].w;
        }
        __stcs((float4*)(out_routed + rbase + j), o);

        if (tid < N_SRC)
            out_alpha[(size_t)r * N_SRC + tid] = alpha[tid];
    }
}

// ---------------------------------------------------------------------------
// kernel_launch
// inputs: [0] values f32 [8,4,2048,2048], [1] w_query f32 [12,2048],
//         [2] key_pos_bias f32 [12,2048], [3] position i32 scalar
// output: routed f32 [4,2048,2048] followed by alpha f32 [4,2048,8]
// ---------------------------------------------------------------------------
extern "C" void kernel_launch(void* const* d_in, const int* in_sizes, int n_in,
                              void* d_out, int out_size) {
    const float* values = (const float*)d_in[0];
    const float* wq     = (const float*)d_in[1];
    const float* bias   = (const float*)d_in[2];
    const int*   pos    = (n_in > 3) ? (const int*)d_in[3] : nullptr;

    float* out_routed = (float*)d_out;
    float* out_alpha  = (float*)d_out + (size_t)B * T * H;

    static int n_cta = 0;
    if (n_cta == 0) {
        int dev = 0, nsm = 148;
        cudaGetDevice(&dev);
        cudaDeviceGetAttribute(&nsm, cudaDevAttrMultiProcessorCount, dev);
        n_cta = nsm * CTAS_PER_SM;
    }

    router_kernel<<<n_cta, THREADS>>>(values, wq, bias, pos,
                                      out_routed, out_alpha, n_cta);
}